// round 5
// baseline (speedup 1.0000x reference)
#include <cuda_runtime.h>

#define NTHREADS 256

// Shapes: x:[8,4096,768]  n=4, D=768 (p_d=192), d=192 (q_d=48)
// phm_rule_*: [4,4,4] flat i*16+a*4+c
// W_left_d : [4,192,1] -> u_d[i][p]   (i*192+p)
// W_right_d: [4,1,48]  -> v_d[i][s]   (i*48+s)
// W_left_u : [4,48,1]  -> u_u[i][p]   (i*48+p)
// W_right_u: [4,1,192] -> v_u[i][s]   (i*192+s)

__global__ __launch_bounds__(NTHREADS, 8)
void phm_adapter_kernel(const float* __restrict__ x,
                        const float* __restrict__ phm_d,
                        const float* __restrict__ Ud,
                        const float* __restrict__ Vd,
                        const float* __restrict__ bias_d,
                        const float* __restrict__ phm_u,
                        const float* __restrict__ Uu,
                        const float* __restrict__ Vu,
                        const float* __restrict__ bias_u,
                        float* __restrict__ out)
{
    const int tok = blockIdx.x;
    const float4* __restrict__ xr4 = (const float4*)(x + (size_t)tok * 768);
    float4* __restrict__ orow4 = (float4*)(out + (size_t)tok * 768);

    __shared__ float sx[768];
    __shared__ float st[16];    // t[a*4+i]
    __shared__ float sg[16];    // g[i*4+c]
    __shared__ float sz[192];   // gelu'd hidden
    __shared__ float stu[16];
    __shared__ float sgu[16];

    const int tid = threadIdx.x;

    // ---- load x row: 192 threads x float4 = 768 floats, coalesced ----
    if (tid < 192) {
        ((float4*)sx)[tid] = xr4[tid];
    }
    __syncthreads();

    // ---- t[a][i] = sum_p x[a*192+p] * Ud[i][p] : 16 groups of 16 threads ----
    {
        const int pair = tid >> 4;          // 0..15
        const int a = pair >> 2;
        const int i = pair & 3;
        const int j = tid & 15;
        float s = 0.0f;
        #pragma unroll
        for (int p = j; p < 192; p += 16)
            s += sx[a * 192 + p] * Ud[i * 192 + p];
        #pragma unroll
        for (int off = 8; off; off >>= 1)
            s += __shfl_down_sync(0xffffffffu, s, off, 16);
        if (j == 0) st[a * 4 + i] = s;
    }
    __syncthreads();

    // ---- g[i][c] = sum_a t[a][i] * phm_d[i,a,c] ----
    if (tid < 16) {
        const int i = tid >> 2, c = tid & 3;
        float s = 0.0f;
        #pragma unroll
        for (int a = 0; a < 4; a++)
            s += st[a * 4 + i] * phm_d[i * 16 + a * 4 + c];
        sg[i * 4 + c] = s;
    }
    __syncthreads();

    // ---- z[c*48+s] = gelu( sum_i g[i][c]*Vd[i][s] + bias_d ) ----
    if (tid < 192) {
        const int c = tid / 48, s = tid % 48;
        float v = bias_d[tid];
        #pragma unroll
        for (int i = 0; i < 4; i++)
            v += sg[i * 4 + c] * Vd[i * 48 + s];
        const float u = v;
        const float g = 0.5f * u * (1.0f + tanhf(0.7978845608028654f *
                                   (u + 0.044715f * u * u * u)));
        sz[tid] = g;
    }
    __syncthreads();

    // ---- t_u[a][i] = sum_p z[a*48+p] * Uu[i][p] : 16 groups of 16 threads ----
    {
        const int pair = tid >> 4;
        const int a = pair >> 2;
        const int i = pair & 3;
        const int j = tid & 15;
        float s = 0.0f;
        #pragma unroll
        for (int p = j; p < 48; p += 16)
            s += sz[a * 48 + p] * Uu[i * 48 + p];
        #pragma unroll
        for (int off = 8; off; off >>= 1)
            s += __shfl_down_sync(0xffffffffu, s, off, 16);
        if (j == 0) stu[a * 4 + i] = s;
    }
    __syncthreads();

    // ---- g_u[i][c] = sum_a t_u[a][i] * phm_u[i,a,c] ----
    if (tid < 16) {
        const int i = tid >> 2, c = tid & 3;
        float s = 0.0f;
        #pragma unroll
        for (int a = 0; a < 4; a++)
            s += stu[a * 4 + i] * phm_u[i * 16 + a * 4 + c];
        sgu[i * 4 + c] = s;
    }
    __syncthreads();

    // ---- out[c*192+s] = sum_i g_u[i][c]*Vu[i][s] + bias_u ----
    // 192 threads, 4 consecutive outputs each; c is constant within a quad (4|192).
    if (tid < 192) {
        const int idx = tid * 4;
        const int c = idx / 192;
        const int s = idx % 192;
        const float g0 = sgu[c];
        const float g1 = sgu[4 + c];
        const float g2 = sgu[8 + c];
        const float g3 = sgu[12 + c];
        float4 v;
        v.x = bias_u[idx + 0] + g0 * Vu[s + 0]       + g1 * Vu[192 + s + 0]
            + g2 * Vu[384 + s + 0] + g3 * Vu[576 + s + 0];
        v.y = bias_u[idx + 1] + g0 * Vu[s + 1]       + g1 * Vu[192 + s + 1]
            + g2 * Vu[384 + s + 1] + g3 * Vu[576 + s + 1];
        v.z = bias_u[idx + 2] + g0 * Vu[s + 2]       + g1 * Vu[192 + s + 2]
            + g2 * Vu[384 + s + 2] + g3 * Vu[576 + s + 2];
        v.w = bias_u[idx + 3] + g0 * Vu[s + 3]       + g1 * Vu[192 + s + 3]
            + g2 * Vu[384 + s + 3] + g3 * Vu[576 + s + 3];
        orow4[tid] = v;
    }
}

extern "C" void kernel_launch(void* const* d_in, const int* in_sizes, int n_in,
                              void* d_out, int out_size)
{
    const float* x      = (const float*)d_in[0];
    const float* phm_d  = (const float*)d_in[1];
    const float* Ud     = (const float*)d_in[2];
    const float* Vd     = (const float*)d_in[3];
    const float* bias_d = (const float*)d_in[4];
    const float* phm_u  = (const float*)d_in[5];
    const float* Uu     = (const float*)d_in[6];
    const float* Vu     = (const float*)d_in[7];
    const float* bias_u = (const float*)d_in[8];
    float* out = (float*)d_out;

    const int ntok = in_sizes[0] / 768;   // 32768
    phm_adapter_kernel<<<ntok, NTHREADS>>>(x, phm_d, Ud, Vd, bias_d,
                                           phm_u, Uu, Vu, bias_u, out);
}

// round 8
// speedup vs baseline: 1.8721x; 1.8721x over previous
#include <cuda_runtime.h>

// x:[8,4096,768]  n=4, D=768 (p=192), d=192 (q=48)
// phm_rule_*: [4,4,4] flat i*16+a*4+c
// Ud = W_left_d : [4,192] (i*192+p)   Vd = W_right_d: [4,48] (i*48+s)
// Uu = W_left_u : [4,48]  (i*48+p)    Vu = W_right_u: [4,192] (i*192+s)
//
// Warp-per-token. Rank-1 factors collapse each PHM layer to:
//   t[a][i] = sum_p x[a*192+p]*Ud[i][p]         (16 dots of 192)
//   g[i][c] = sum_a t[a][i]*phm[i,a,c]          (tiny)
//   z[c*48+s] = gelu(sum_i g[i][c]*Vd[i][s]+b)  (192)
// then same for up-projection (48-length dots, 768 outputs).

#define WARPS_PER_CTA 8
#define SQ2PI 0.7978845608028654f

__device__ __forceinline__ float dot4(float4 a, float4 b) {
    return a.x * b.x + a.y * b.y + a.z * b.z + a.w * b.w;
}

__device__ __forceinline__ float gelu_new(float u) {
    return 0.5f * u * (1.0f + tanhf(SQ2PI * (u + 0.044715f * u * u * u)));
}

__global__ __launch_bounds__(WARPS_PER_CTA * 32)
void phm_adapter_kernel(const float* __restrict__ x,
                        const float* __restrict__ phm_d,
                        const float* __restrict__ Ud,
                        const float* __restrict__ Vd,
                        const float* __restrict__ bias_d,
                        const float* __restrict__ phm_u,
                        const float* __restrict__ Uu,
                        const float* __restrict__ Vu,
                        const float* __restrict__ bias_u,
                        float* __restrict__ out,
                        int ntok)
{
    const int warp = threadIdx.x >> 5;
    const int lane = threadIdx.x & 31;
    const int tok  = blockIdx.x * WARPS_PER_CTA + warp;
    if (tok >= ntok) return;

    __shared__ float4 zbuf[WARPS_PER_CTA][48];   // per-warp hidden row (192 floats)

    const float4* __restrict__ xr4 = (const float4*)x + (size_t)tok * 192;
    float4* __restrict__ or4       = (float4*)out + (size_t)tok * 192;
    const float4* __restrict__ Ud4 = (const float4*)Ud;   // [i*48 + p4]
    const float4* __restrict__ Vd4 = (const float4*)Vd;   // [i*12 + s4]
    const float4* __restrict__ Uu4 = (const float4*)Uu;   // [i*12 + p4]
    const float4* __restrict__ Vu4 = (const float4*)Vu;   // [i*48 + s4]
    const float4* __restrict__ bd4 = (const float4*)bias_d; // 48
    const float4* __restrict__ bu4 = (const float4*)bias_u; // 192

    const unsigned FULL = 0xffffffffu;
    const int f0 = lane;          // float4-position slot 0 (always < 48)
    const int f1 = lane + 32;     // slot 1, active for lane < 16
    const bool s1 = (lane < 16);

    // ---- load x row: each lane holds positions f0 (and f1) for all 4 a-blocks ----
    float4 xv0[4], xv1[4];
    #pragma unroll
    for (int a = 0; a < 4; a++) xv0[a] = xr4[a * 48 + f0];
    if (s1) {
        #pragma unroll
        for (int a = 0; a < 4; a++) xv1[a] = xr4[a * 48 + f1];
    }

    // ---- stage 1: t[a][i], 4x4 register-blocked (x read 1x, Ud read 1x) ----
    float t[16];
    {
        float4 u0[4], u1[4];
        #pragma unroll
        for (int i = 0; i < 4; i++) u0[i] = Ud4[i * 48 + f0];
        if (s1) {
            #pragma unroll
            for (int i = 0; i < 4; i++) u1[i] = Ud4[i * 48 + f1];
        }
        #pragma unroll
        for (int a = 0; a < 4; a++)
            #pragma unroll
            for (int i = 0; i < 4; i++) {
                float s = dot4(xv0[a], u0[i]);
                if (s1) s += dot4(xv1[a], u1[i]);
                t[a * 4 + i] = s;
            }
    }
    // warp butterfly reduce (all lanes end with full sums)
    #pragma unroll
    for (int off = 16; off; off >>= 1)
        #pragma unroll
        for (int j = 0; j < 16; j++)
            t[j] += __shfl_xor_sync(FULL, t[j], off);

    // ---- stage 2: g[i][c] on lanes 0..15, then broadcast ----
    float gval = 0.0f;
    if (lane < 16) {
        const int i = lane >> 2, c = lane & 3;
        #pragma unroll
        for (int a = 0; a < 4; a++)
            gval += t[a * 4 + i] * phm_d[i * 16 + a * 4 + c];
    }
    float gall[16];
    #pragma unroll
    for (int j = 0; j < 16; j++)
        gall[j] = __shfl_sync(FULL, gval, j);   // gall[i*4+c]

    // ---- stage 3: z = gelu(bias_d + sum_i g[i][c]*Vd[i][s]) -> smem ----
    {
        const int c0 = f0 / 12, sq0 = f0 % 12;
        float4 v = bd4[f0];
        #pragma unroll
        for (int i = 0; i < 4; i++) {
            const float gi = gall[i * 4 + c0];
            const float4 w = Vd4[i * 12 + sq0];
            v.x += gi * w.x; v.y += gi * w.y; v.z += gi * w.z; v.w += gi * w.w;
        }
        v.x = gelu_new(v.x); v.y = gelu_new(v.y); v.z = gelu_new(v.z); v.w = gelu_new(v.w);
        zbuf[warp][f0] = v;
        if (s1) {
            const int c1 = f1 / 12, sq1 = f1 % 12;
            float4 v2 = bd4[f1];
            #pragma unroll
            for (int i = 0; i < 4; i++) {
                const float gi = gall[i * 4 + c1];
                const float4 w = Vd4[i * 12 + sq1];
                v2.x += gi * w.x; v2.y += gi * w.y; v2.z += gi * w.z; v2.w += gi * w.w;
            }
            v2.x = gelu_new(v2.x); v2.y = gelu_new(v2.y);
            v2.z = gelu_new(v2.z); v2.w = gelu_new(v2.w);
            zbuf[warp][f1] = v2;
        }
    }
    __syncwarp(FULL);

    // ---- stage 4: tu[a][i] = sum_p z[a*48+p]*Uu[i][p], 4x4 blocked on lanes 0..11 ----
    float tu[16];
    #pragma unroll
    for (int j = 0; j < 16; j++) tu[j] = 0.0f;
    if (lane < 12) {
        float4 zq[4], uu[4];
        #pragma unroll
        for (int a = 0; a < 4; a++) zq[a] = zbuf[warp][a * 12 + lane];
        #pragma unroll
        for (int i = 0; i < 4; i++) uu[i] = Uu4[i * 12 + lane];
        #pragma unroll
        for (int a = 0; a < 4; a++)
            #pragma unroll
            for (int i = 0; i < 4; i++)
                tu[a * 4 + i] = dot4(zq[a], uu[i]);
    }
    // active lanes 0..11 all sit in lower half-warp: 4-stage butterfly suffices
    #pragma unroll
    for (int off = 8; off; off >>= 1)
        #pragma unroll
        for (int j = 0; j < 16; j++)
            tu[j] += __shfl_xor_sync(FULL, tu[j], off);

    // ---- stage 2u: gu[i][c] on lanes 0..15, broadcast ----
    float guval = 0.0f;
    if (lane < 16) {
        const int i = lane >> 2, c = lane & 3;
        #pragma unroll
        for (int a = 0; a < 4; a++)
            guval += tu[a * 4 + i] * phm_u[i * 16 + a * 4 + c];
    }
    float guall[16];
    #pragma unroll
    for (int j = 0; j < 16; j++)
        guall[j] = __shfl_sync(FULL, guval, j);

    // ---- stage 5: out[c*192+s] = bias_u + sum_i gu[i][c]*Vu[i][s] (Vu read 1x) ----
    {
        float4 vu0[4], vu1[4];
        #pragma unroll
        for (int i = 0; i < 4; i++) vu0[i] = Vu4[i * 48 + f0];
        if (s1) {
            #pragma unroll
            for (int i = 0; i < 4; i++) vu1[i] = Vu4[i * 48 + f1];
        }
        #pragma unroll
        for (int c = 0; c < 4; c++) {
            float4 v = bu4[c * 48 + f0];
            #pragma unroll
            for (int i = 0; i < 4; i++) {
                const float gi = guall[i * 4 + c];
                v.x += gi * vu0[i].x; v.y += gi * vu0[i].y;
                v.z += gi * vu0[i].z; v.w += gi * vu0[i].w;
            }
            or4[c * 48 + f0] = v;
        }
        if (s1) {
            #pragma unroll
            for (int c = 0; c < 4; c++) {
                float4 v = bu4[c * 48 + f1];
                #pragma unroll
                for (int i = 0; i < 4; i++) {
                    const float gi = guall[i * 4 + c];
                    v.x += gi * vu1[i].x; v.y += gi * vu1[i].y;
                    v.z += gi * vu1[i].z; v.w += gi * vu1[i].w;
                }
                or4[c * 48 + f1] = v;
            }
        }
    }
}

extern "C" void kernel_launch(void* const* d_in, const int* in_sizes, int n_in,
                              void* d_out, int out_size)
{
    const float* x      = (const float*)d_in[0];
    const float* phm_d  = (const float*)d_in[1];
    const float* Ud     = (const float*)d_in[2];
    const float* Vd     = (const float*)d_in[3];
    const float* bias_d = (const float*)d_in[4];
    const float* phm_u  = (const float*)d_in[5];
    const float* Uu     = (const float*)d_in[6];
    const float* Vu     = (const float*)d_in[7];
    const float* bias_u = (const float*)d_in[8];
    float* out = (float*)d_out;

    const int ntok = in_sizes[0] / 768;   // 32768
    const int blocks = (ntok + WARPS_PER_CTA - 1) / WARPS_PER_CTA;
    phm_adapter_kernel<<<blocks, WARPS_PER_CTA * 32>>>(x, phm_d, Ud, Vd, bias_d,
                                                       phm_u, Uu, Vu, bias_u, out, ntok);
}

// round 12
// speedup vs baseline: 2.4656x; 1.3170x over previous
#include <cuda_runtime.h>

// x:[8,4096,768]  n=4, D=768 (p=192), d=192 (q=48)
// phm_rule_*: [4,4,4] flat i*16+a*4+c
// Ud = W_left_d : [4,192] (i*192+p)   Vd = W_right_d: [4,48] (i*48+s)
// Uu = W_left_u : [4,48]  (i*48+p)    Vu = W_right_u: [4,192] (i*192+s)
//
// Warp-per-token, rank-1 collapse:
//   t[a][i]  = sum_p x[a*192+p]*Ud[i][p]
//   g[i][c]  = sum_a t[a][i]*phm[i,a,c]
//   z[c*48+s]= gelu(sum_i g[i][c]*Vd[i][s]+bias_d)
//   (repeat with Uu/phm_u/Vu/bias_u for the 768-wide output)
//
// Reductions use 8-lane groups (group = a). Dynamic selection is done via the
// SHFL source-lane operand (data), never via runtime register-array indexing,
// so nothing spills to local memory.

#define WARPS_PER_CTA 8
#define FULLMASK 0xffffffffu
#define SQ2PI 0.7978845608028654f

__device__ __forceinline__ float dot4(float4 a, float4 b) {
    return a.x * b.x + a.y * b.y + a.z * b.z + a.w * b.w;
}

__device__ __forceinline__ float tanh_fast(float v) {
    float y;
    asm("tanh.approx.f32 %0, %1;" : "=f"(y) : "f"(v));
    return y;
}

__device__ __forceinline__ float gelu_new(float u) {
    return 0.5f * u * (1.0f + tanh_fast(SQ2PI * (u + 0.044715f * u * u * u)));
}

__global__ __launch_bounds__(WARPS_PER_CTA * 32, 4)
void phm_adapter_kernel(const float* __restrict__ x,
                        const float* __restrict__ phm_d,
                        const float* __restrict__ Ud,
                        const float* __restrict__ Vd,
                        const float* __restrict__ bias_d,
                        const float* __restrict__ phm_u,
                        const float* __restrict__ Uu,
                        const float* __restrict__ Vu,
                        const float* __restrict__ bias_u,
                        float* __restrict__ out,
                        int ntok)
{
    const int warp = threadIdx.x >> 5;
    const int lane = threadIdx.x & 31;
    const int tok  = blockIdx.x * WARPS_PER_CTA + warp;
    if (tok >= ntok) return;                 // whole warp uniform

    __shared__ float4 zbuf[WARPS_PER_CTA][48];

    const float4* __restrict__ xr4 = (const float4*)x + (size_t)tok * 192;
    float4* __restrict__ or4       = (float4*)out + (size_t)tok * 192;
    const float4* __restrict__ Ud4 = (const float4*)Ud;     // [i*48 + p4]
    const float4* __restrict__ Vd4 = (const float4*)Vd;     // [i*12 + s4]
    const float4* __restrict__ Uu4 = (const float4*)Uu;     // [i*12 + p4]
    const float4* __restrict__ Vu4 = (const float4*)Vu;     // [i*48 + s4]
    const float4* __restrict__ bd4 = (const float4*)bias_d; // 48 quads
    const float4* __restrict__ bu4 = (const float4*)bias_u; // 192 quads

    const int grp = lane >> 3;      // a-block owned by this 8-lane group
    const int sub = lane & 7;
    const int i2  = (lane >> 2) & 3;  // (i,c) role for lanes 0..15 (mirrored above)
    const int c2  = lane & 3;

    // ================= stage 1: t[a][i] partials, group-of-8 =================
    float tp0 = 0.f, tp1 = 0.f, tp2 = 0.f, tp3 = 0.f;
    #pragma unroll
    for (int k = 0; k < 6; k++) {
        const int q = sub + 8 * k;            // quad 0..47 within a-block
        const float4 xq = xr4[grp * 48 + q];
        tp0 += dot4(xq, Ud4[0 * 48 + q]);
        tp1 += dot4(xq, Ud4[1 * 48 + q]);
        tp2 += dot4(xq, Ud4[2 * 48 + q]);
        tp3 += dot4(xq, Ud4[3 * 48 + q]);
    }
    #pragma unroll
    for (int off = 4; off; off >>= 1) {
        tp0 += __shfl_xor_sync(FULLMASK, tp0, off);
        tp1 += __shfl_xor_sync(FULLMASK, tp1, off);
        tp2 += __shfl_xor_sync(FULLMASK, tp2, off);
        tp3 += __shfl_xor_sync(FULLMASK, tp3, off);
    }
    // consolidate: lane grp*8+i carries t[grp][i] (3-SEL chain, static regs)
    const int s3 = sub & 3;
    float tsingle = (s3 == 0) ? tp0 : (s3 == 1) ? tp1 : (s3 == 2) ? tp2 : tp3;

    // ============ stage 2: g[i][c] on lanes 0..15 (mirrored 16..31) ==========
    float gval = 0.f;
    #pragma unroll
    for (int a = 0; a < 4; a++) {
        const float ta = __shfl_sync(FULLMASK, tsingle, a * 8 + i2);
        gval += ta * phm_d[i2 * 16 + a * 4 + c2];
    }

    // ========== stage 3: z quad f = gelu(bias + sum_i g[i][c]*Vd) ===========
    // slot 0: quad f0 = lane (0..31); slot 1: quad f1 = lane+32 (lanes 0..15)
    const int c0  = lane / 12;
    const int sq0 = lane - c0 * 12;
    float gz0[4], gz1[4];
    #pragma unroll
    for (int i = 0; i < 4; i++)
        gz0[i] = __shfl_sync(FULLMASK, gval, i * 4 + c0);
    const int f1  = lane + 32;
    const int c1m = f1 / 12;                 // valid for lanes<16; benign above
    #pragma unroll
    for (int i = 0; i < 4; i++)
        gz1[i] = __shfl_sync(FULLMASK, gval, (i * 4 + c1m) & 31);
    {
        float4 v = bd4[lane];
        #pragma unroll
        for (int i = 0; i < 4; i++) {
            const float gi = gz0[i];
            const float4 w = Vd4[i * 12 + sq0];
            v.x += gi * w.x; v.y += gi * w.y; v.z += gi * w.z; v.w += gi * w.w;
        }
        v.x = gelu_new(v.x); v.y = gelu_new(v.y);
        v.z = gelu_new(v.z); v.w = gelu_new(v.w);
        zbuf[warp][lane] = v;
    }
    if (lane < 16) {
        const int sq1 = f1 - c1m * 12;
        float4 v = bd4[f1];
        #pragma unroll
        for (int i = 0; i < 4; i++) {
            const float gi = gz1[i];
            const float4 w = Vd4[i * 12 + sq1];
            v.x += gi * w.x; v.y += gi * w.y; v.z += gi * w.z; v.w += gi * w.w;
        }
        v.x = gelu_new(v.x); v.y = gelu_new(v.y);
        v.z = gelu_new(v.z); v.w = gelu_new(v.w);
        zbuf[warp][f1] = v;
    }
    __syncwarp(FULLMASK);

    // ========= stage 4: tu[a][i] = z_a . Uu_i (len 48), group-of-8 ==========
    float up0, up1, up2, up3;
    {
        const float4 zq = zbuf[warp][grp * 12 + sub];  // sub 0..7 < 12
        up0 = dot4(zq, Uu4[0 * 12 + sub]);
        up1 = dot4(zq, Uu4[1 * 12 + sub]);
        up2 = dot4(zq, Uu4[2 * 12 + sub]);
        up3 = dot4(zq, Uu4[3 * 12 + sub]);
    }
    if (sub < 4) {
        const int q = sub + 8;
        const float4 zq = zbuf[warp][grp * 12 + q];
        up0 += dot4(zq, Uu4[0 * 12 + q]);
        up1 += dot4(zq, Uu4[1 * 12 + q]);
        up2 += dot4(zq, Uu4[2 * 12 + q]);
        up3 += dot4(zq, Uu4[3 * 12 + q]);
    }
    #pragma unroll
    for (int off = 4; off; off >>= 1) {
        up0 += __shfl_xor_sync(FULLMASK, up0, off);
        up1 += __shfl_xor_sync(FULLMASK, up1, off);
        up2 += __shfl_xor_sync(FULLMASK, up2, off);
        up3 += __shfl_xor_sync(FULLMASK, up3, off);
    }
    float tusingle = (s3 == 0) ? up0 : (s3 == 1) ? up1 : (s3 == 2) ? up2 : up3;

    // ================== stage 2u: gu[i][c] + full broadcast ==================
    float guval = 0.f;
    #pragma unroll
    for (int a = 0; a < 4; a++) {
        const float ta = __shfl_sync(FULLMASK, tusingle, a * 8 + i2);
        guval += ta * phm_u[i2 * 16 + a * 4 + c2];
    }
    float guall[16];
    #pragma unroll
    for (int j = 0; j < 16; j++)
        guall[j] = __shfl_sync(FULLMASK, guval, j);   // guall[i*4+c]

    // ===== stage 5: out[c*192 + s] = bias_u + sum_i gu[i][c]*Vu[i][s] ========
    // slot 0: s-quad = lane, all 4 c; slot 1: s-quad = lane+32, lanes<16.
    {
        float4 vu[4];
        #pragma unroll
        for (int i = 0; i < 4; i++) vu[i] = Vu4[i * 48 + lane];
        #pragma unroll
        for (int c = 0; c < 4; c++) {
            float4 v = bu4[c * 48 + lane];
            #pragma unroll
            for (int i = 0; i < 4; i++) {
                const float gi = guall[i * 4 + c];
                v.x += gi * vu[i].x; v.y += gi * vu[i].y;
                v.z += gi * vu[i].z; v.w += gi * vu[i].w;
            }
            or4[c * 48 + lane] = v;
        }
    }
    if (lane < 16) {
        const int sq = lane + 32;
        float4 vu[4];
        #pragma unroll
        for (int i = 0; i < 4; i++) vu[i] = Vu4[i * 48 + sq];
        #pragma unroll
        for (int c = 0; c < 4; c++) {
            float4 v = bu4[c * 48 + sq];
            #pragma unroll
            for (int i = 0; i < 4; i++) {
                const float gi = guall[i * 4 + c];
                v.x += gi * vu[i].x; v.y += gi * vu[i].y;
                v.z += gi * vu[i].z; v.w += gi * vu[i].w;
            }
            or4[c * 48 + sq] = v;
        }
    }
}

extern "C" void kernel_launch(void* const* d_in, const int* in_sizes, int n_in,
                              void* d_out, int out_size)
{
    const float* x      = (const float*)d_in[0];
    const float* phm_d  = (const float*)d_in[1];
    const float* Ud     = (const float*)d_in[2];
    const float* Vd     = (const float*)d_in[3];
    const float* bias_d = (const float*)d_in[4];
    const float* phm_u  = (const float*)d_in[5];
    const float* Uu     = (const float*)d_in[6];
    const float* Vu     = (const float*)d_in[7];
    const float* bias_u = (const float*)d_in[8];
    float* out = (float*)d_out;

    const int ntok = in_sizes[0] / 768;   // 32768
    const int blocks = (ntok + WARPS_PER_CTA - 1) / WARPS_PER_CTA;
    phm_adapter_kernel<<<blocks, WARPS_PER_CTA * 32>>>(x, phm_d, Ud, Vd, bias_d,
                                                       phm_u, Uu, Vu, bias_u, out, ntok);
}